// round 16
// baseline (speedup 1.0000x reference)
#include <cuda_runtime.h>
#include <cuda_fp16.h>
#include <mma.h>
#include <cstdint>

using namespace nvcuda;

// ---------------------------------------------------------------------------
// LePE attention, fp16 tensor-core end-to-end (R16):
//   GEMM CTA tile 256m x 192n (12 warps, 64x64 warp tiles) -> halves B
//   re-read L2 traffic; lepe reads fp16 x.
// B=16, H=W=64, C=384, HEADS=12, hd=32, IDX=0 (vertical strips).
// ---------------------------------------------------------------------------

#define C_DIM   384
#define N_HEADS 12
#define HD      32
#define B_DIM   16
#define NTOK    4096
#define M_TOTAL 65536
#define QKV_N   1152

// Scratch (fp16)
__device__ __half g_x_h[(size_t)M_TOTAL * C_DIM];
__device__ __half g_qkvw_h[(size_t)QKV_N * C_DIM];
__device__ __half g_projw_h[(size_t)C_DIM * C_DIM];
__device__ __half g_qkv_h[(size_t)M_TOTAL * QKV_N];
__device__ __half g_comb_h[(size_t)M_TOTAL * C_DIM];

#define BK    32
#define PAD_H 40   // halves per smem row (80B)

__device__ __forceinline__ uint4 pack8(const float4 f0, const float4 f1) {
    __half2 h0 = __floats2half2_rn(f0.x, f0.y);
    __half2 h1 = __floats2half2_rn(f0.z, f0.w);
    __half2 h2 = __floats2half2_rn(f1.x, f1.y);
    __half2 h3 = __floats2half2_rn(f1.z, f1.w);
    uint4 u;
    u.x = *reinterpret_cast<uint32_t*>(&h0);
    u.y = *reinterpret_cast<uint32_t*>(&h1);
    u.z = *reinterpret_cast<uint32_t*>(&h2);
    u.w = *reinterpret_cast<uint32_t*>(&h3);
    return u;
}

__global__ __launch_bounds__(256) void cvt_f32_f16_kernel(
    const float* __restrict__ src, __half* __restrict__ dst, int n)
{
    const int i = (blockIdx.x * 256 + threadIdx.x) * 8;
    if (i < n) {
        float4 a = *(const float4*)(src + i);
        float4 b = *(const float4*)(src + i + 4);
        *(uint4*)(dst + i) = pack8(a, b);
    }
}

// ---------------------------------------------------------------------------
// GEMM (fp16 in): D[m,n] = sum_k A[m,k] * Bw[n,k]
// CTA tile (64*NWM)m x (64*NWN)n, NWM*NWN warps, warp tile 64x64
// (4x4 m16n16k16). BK=32 double-buffered cp.async.
// Grid: blockIdx.x = n-block (fast, L2 A-reuse), blockIdx.y = m-block.
// OUT_HALF: D fp16 no bias; else D fp32 + bias.
// ---------------------------------------------------------------------------
template <int NWM, int NWN, bool OUT_HALF>
__global__ __launch_bounds__(32 * NWM * NWN)
void gemm_h_kernel(const __half* __restrict__ A, const __half* __restrict__ Bw,
                   const float* __restrict__ bias, void* __restrict__ Dx,
                   int ldD)
{
    constexpr int NT      = 32 * NWM * NWN;   // threads
    constexpr int M_TILE  = 64 * NWM;
    constexpr int N_TILE  = 64 * NWN;
    constexpr int A_UNITS = M_TILE * 4;       // 16B units per A chunk
    constexpr int B_UNITS = N_TILE * 4;

    __shared__ __half As[2][M_TILE * PAD_H];
    __shared__ __half Bs[2][N_TILE * PAD_H];

    const int tid  = threadIdx.x;
    const int lane = tid & 31;
    const int warp = tid >> 5;                // 0 .. NWM*NWN-1
    const int warpM = warp / NWN;             // 0..NWM-1
    const int warpN = warp % NWN;             // 0..NWN-1
    const int n0 = blockIdx.x * N_TILE;       // n fast
    const int m0 = blockIdx.y * M_TILE;

    const __half* aTile = A + (size_t)m0 * C_DIM;
    const __half* bTile = Bw + (size_t)n0 * C_DIM;

    uint32_t smA[2], smB[2];
#pragma unroll
    for (int bfi = 0; bfi < 2; bfi++) {
        smA[bfi] = (uint32_t)__cvta_generic_to_shared(&As[bfi][0]);
        smB[bfi] = (uint32_t)__cvta_generic_to_shared(&Bs[bfi][0]);
    }

    wmma::fragment<wmma::accumulator, 16, 16, 16, float> acc[4][4];
#pragma unroll
    for (int tr = 0; tr < 4; tr++)
#pragma unroll
        for (int tc = 0; tc < 4; tc++)
            wmma::fill_fragment(acc[tr][tc], 0.0f);

    const int NCHUNK = C_DIM / BK;  // 12

    auto issue_chunk = [&](int c, int bfi) {
        const int k0g = c * BK;
#pragma unroll
        for (int u = tid; u < A_UNITS; u += NT) {
            const int row = u >> 2, q = u & 3;
            asm volatile("cp.async.cg.shared.global [%0], [%1], 16;"
                :: "r"(smA[bfi] + (row * PAD_H + q * 8) * 2),
                   "l"(aTile + (size_t)row * C_DIM + k0g + q * 8) : "memory");
        }
#pragma unroll
        for (int u = tid; u < B_UNITS; u += NT) {
            const int row = u >> 2, q = u & 3;
            asm volatile("cp.async.cg.shared.global [%0], [%1], 16;"
                :: "r"(smB[bfi] + (row * PAD_H + q * 8) * 2),
                   "l"(bTile + (size_t)row * C_DIM + k0g + q * 8) : "memory");
        }
        asm volatile("cp.async.commit_group;" ::: "memory");
    };

    issue_chunk(0, 0);

    for (int c = 0; c < NCHUNK; c++) {
        asm volatile("cp.async.wait_group 0;" ::: "memory");
        __syncthreads();

        if (c + 1 < NCHUNK) issue_chunk(c + 1, (c + 1) & 1);

        const __half* sa = As[c & 1];
        const __half* sb = Bs[c & 1];
#pragma unroll
        for (int ks = 0; ks < 2; ks++) {
            const int k0 = ks * 16;
            wmma::fragment<wmma::matrix_a, 16, 16, 16, __half,
                           wmma::row_major> af[4];
#pragma unroll
            for (int tr = 0; tr < 4; tr++)
                wmma::load_matrix_sync(af[tr],
                    sa + (warpM * 64 + tr * 16) * PAD_H + k0, PAD_H);
#pragma unroll
            for (int tc = 0; tc < 4; tc++) {
                wmma::fragment<wmma::matrix_b, 16, 16, 16, __half,
                               wmma::col_major> bf;
                wmma::load_matrix_sync(bf,
                    sb + (warpN * 64 + tc * 16) * PAD_H + k0, PAD_H);
#pragma unroll
                for (int tr = 0; tr < 4; tr++)
                    wmma::mma_sync(acc[tr][tc], af[tr], bf, acc[tr][tc]);
            }
        }
    }
    __syncthreads();

    // epilogue: per-warp 16x16 fp32 staging in As region
    float* stage = reinterpret_cast<float*>(&As[0][0]) + warp * 256;
#pragma unroll
    for (int tr = 0; tr < 4; tr++) {
#pragma unroll
        for (int tc = 0; tc < 4; tc++) {
            const int mBase = m0 + warpM * 64 + tr * 16;
            const int nBase = n0 + warpN * 64 + tc * 16;
            wmma::store_matrix_sync(stage, acc[tr][tc], 16, wmma::mem_row_major);
            __syncwarp();
            if (OUT_HALF) {
                __half* Dh = (__half*)Dx;
#pragma unroll
                for (int t = 0; t < 2; t++) {
                    const int idx = t * 32 + lane;
                    const int r  = idx >> 2;
                    const int c4 = idx & 3;
                    const float* sp = stage + r * 16 + c4 * 4;
                    __half2 h0 = __floats2half2_rn(sp[0], sp[1]);
                    __half2 h1 = __floats2half2_rn(sp[2], sp[3]);
                    uint2 u;
                    u.x = *reinterpret_cast<uint32_t*>(&h0);
                    u.y = *reinterpret_cast<uint32_t*>(&h1);
                    *(uint2*)&Dh[(size_t)(mBase + r) * ldD + nBase + c4 * 4] = u;
                }
            } else {
                float* Df = (float*)Dx;
#pragma unroll
                for (int t = 0; t < 2; t++) {
                    const int idx = t * 32 + lane;
                    const int r  = idx >> 2;
                    const int c4 = idx & 3;
                    float4 v = *(const float4*)(stage + r * 16 + c4 * 4);
                    const float4 b4 = *(const float4*)&bias[nBase + c4 * 4];
                    v.x += b4.x; v.y += b4.y; v.z += b4.z; v.w += b4.w;
                    *(float4*)&Df[(size_t)(mBase + r) * ldD + nBase + c4 * 4] = v;
                }
            }
            __syncwarp();
        }
    }
}

// ---------------------------------------------------------------------------
// Attention via WMMA fp16: one block per (s, head), 128 threads / 4 warps.
// ---------------------------------------------------------------------------
__global__ __launch_bounds__(128) void attn_kernel()
{
    __shared__ __half Qh[64][PAD_H];
    __shared__ __half Kh[64][PAD_H];
    __shared__ __half Vh[64][PAD_H];
    __shared__ float  S[64][68];
    __shared__ __half Ph[64][72];

    const int g    = blockIdx.x;
    const int tid  = threadIdx.x;
    const int warp = tid >> 5, lane = tid & 31;
    const int s    = g / N_HEADS;
    const int head = g - s * N_HEADS;
    const int b    = s >> 6;
    const int w    = s & 63;
    const int cBase = head * HD;

    const size_t rowBase = (size_t)(b << 12) + w;
    for (int i = tid; i < 256; i += 128) {
        const int l = i >> 2, grp = i & 3;
        const size_t off = (rowBase + (size_t)l * 64) * QKV_N + cBase + grp * 8;
        *(uint4*)&Qh[l][grp * 8] = *(const uint4*)&g_qkv_h[off];
        *(uint4*)&Kh[l][grp * 8] = *(const uint4*)&g_qkv_h[off + C_DIM];
        *(uint4*)&Vh[l][grp * 8] = *(const uint4*)&g_qkv_h[off + 2 * C_DIM];
    }
    __syncthreads();

    {
        wmma::fragment<wmma::matrix_a, 16, 16, 16, __half, wmma::row_major> aq[2];
        wmma::load_matrix_sync(aq[0], &Qh[warp * 16][0], PAD_H);
        wmma::load_matrix_sync(aq[1], &Qh[warp * 16][16], PAD_H);
#pragma unroll
        for (int nt = 0; nt < 4; nt++) {
            wmma::fragment<wmma::accumulator, 16, 16, 16, float> accS;
            wmma::fill_fragment(accS, 0.0f);
#pragma unroll
            for (int k0 = 0; k0 < 2; k0++) {
                wmma::fragment<wmma::matrix_b, 16, 16, 16, __half,
                               wmma::col_major> bk;
                wmma::load_matrix_sync(bk, &Kh[nt * 16][k0 * 16], PAD_H);
                wmma::mma_sync(accS, aq[k0], bk, accS);
            }
            wmma::store_matrix_sync(&S[warp * 16][nt * 16], accS, 68,
                                    wmma::mem_row_major);
        }
    }
    __syncwarp();

    const float scale = 0.17677669529663687f;
#pragma unroll
    for (int r = 0; r < 16; r++) {
        const int l = warp * 16 + r;
        float v0 = S[l][lane] * scale, v1 = S[l][lane + 32] * scale;
        float mx = fmaxf(v0, v1);
#pragma unroll
        for (int o = 16; o; o >>= 1) mx = fmaxf(mx, __shfl_xor_sync(0xFFFFFFFFu, mx, o));
        const float e0 = __expf(v0 - mx);
        const float e1 = __expf(v1 - mx);
        float sm = e0 + e1;
#pragma unroll
        for (int o = 16; o; o >>= 1) sm += __shfl_xor_sync(0xFFFFFFFFu, sm, o);
        const float inv = 1.f / sm;
        Ph[l][lane]      = __float2half(e0 * inv);
        Ph[l][lane + 32] = __float2half(e1 * inv);
    }
    __syncwarp();

    {
        wmma::fragment<wmma::matrix_a, 16, 16, 16, __half, wmma::row_major> ap[4];
#pragma unroll
        for (int k0 = 0; k0 < 4; k0++)
            wmma::load_matrix_sync(ap[k0], &Ph[warp * 16][k0 * 16], 72);
#pragma unroll
        for (int nt = 0; nt < 2; nt++) {
            wmma::fragment<wmma::accumulator, 16, 16, 16, float> accO;
            wmma::fill_fragment(accO, 0.0f);
#pragma unroll
            for (int k0 = 0; k0 < 4; k0++) {
                wmma::fragment<wmma::matrix_b, 16, 16, 16, __half,
                               wmma::row_major> bv;
                wmma::load_matrix_sync(bv, &Vh[k0 * 16][nt * 16], PAD_H);
                wmma::mma_sync(accO, ap[k0], bv, accO);
            }
            wmma::store_matrix_sync(&S[warp * 16][nt * 16], accO, 68,
                                    wmma::mem_row_major);
        }
    }
    __syncwarp();

    __half* dstBase = g_comb_h +
        ((size_t)(b << 12) + (w << 6) + warp * 16) * C_DIM + cBase;
    for (int idx = lane; idx < 128; idx += 32) {
        const int r = idx >> 3, grp = idx & 7;
        const float* sp = &S[warp * 16 + r][grp * 4];
        __half2 h0 = __floats2half2_rn(sp[0], sp[1]);
        __half2 h1 = __floats2half2_rn(sp[2], sp[3]);
        uint2 u;
        u.x = *reinterpret_cast<uint32_t*>(&h0);
        u.y = *reinterpret_cast<uint32_t*>(&h1);
        *(uint2*)&dstBase[(size_t)r * C_DIM + grp * 4] = u;
    }
}

// ---------------------------------------------------------------------------
// LePE: depthwise 3x3, register-rotation. Reads fp16 g_x_h (halved traffic).
// One block per (b, hh); 384 threads = channels. fp16 += into g_comb_h.
// ---------------------------------------------------------------------------
__global__ __launch_bounds__(C_DIM) void lepe_kernel(
    const float* __restrict__ lw, const float* __restrict__ lb)
{
    const int blk = blockIdx.x;       // b*64 + hh
    const int c   = threadIdx.x;
    const int b   = blk >> 6;
    const int hh  = blk & 63;

    float w9[9];
#pragma unroll
    for (int k = 0; k < 9; k++) w9[k] = lw[c * 9 + k];
    const float bch = lb[c];

    const __half* xrow[3];
    bool valid[3];
#pragma unroll
    for (int j = 0; j < 3; j++) {
        const int y = hh - 1 + j;
        valid[j] = (y >= 0 && y < 64);
        xrow[j] = g_x_h + (size_t)((b << 12) + (y << 6)) * C_DIM + c;
    }

    float xm1[3], x0[3], xp1[3];
#pragma unroll
    for (int j = 0; j < 3; j++) {
        xm1[j] = 0.f;
        x0[j]  = valid[j] ? __half2float(xrow[j][0]) : 0.f;
        xp1[j] = valid[j] ? __half2float(xrow[j][C_DIM]) : 0.f;
    }

    __half* crow = g_comb_h + (size_t)((b << 12) + (hh << 6)) * C_DIM + c;

    for (int ww = 0; ww < 64; ww++) {
        float acc = bch;
#pragma unroll
        for (int j = 0; j < 3; j++)
            acc += xm1[j] * w9[j * 3 + 0] + x0[j] * w9[j * 3 + 1] +
                   xp1[j] * w9[j * 3 + 2];
        const size_t oi = (size_t)ww * C_DIM;
        crow[oi] = __float2half(__half2float(crow[oi]) + acc);

#pragma unroll
        for (int j = 0; j < 3; j++) {
            xm1[j] = x0[j];
            x0[j]  = xp1[j];
            const int nxt = ww + 2;
            xp1[j] = (nxt < 64 && valid[j])
                     ? __half2float(xrow[j][(size_t)nxt * C_DIM]) : 0.f;
        }
    }
}

// ---------------------------------------------------------------------------
extern "C" void kernel_launch(void* const* d_in, const int* in_sizes, int n_in,
                              void* d_out, int out_size)
{
    const float* x      = (const float*)d_in[0];
    const float* qkv_w  = (const float*)d_in[1];
    const float* proj_w = (const float*)d_in[2];
    const float* proj_b = (const float*)d_in[3];
    const float* lepe_w = (const float*)d_in[4];
    const float* lepe_b = (const float*)d_in[5];
    float* out = (float*)d_out;
    (void)in_sizes; (void)n_in; (void)out_size;

    void *x_h, *qkvw_h, *projw_h, *qkv_h, *comb_h;
    cudaGetSymbolAddress(&x_h, g_x_h);
    cudaGetSymbolAddress(&qkvw_h, g_qkvw_h);
    cudaGetSymbolAddress(&projw_h, g_projw_h);
    cudaGetSymbolAddress(&qkv_h, g_qkv_h);
    cudaGetSymbolAddress(&comb_h, g_comb_h);

    const int nx = M_TOTAL * C_DIM;
    const int nq = QKV_N * C_DIM;
    const int np = C_DIM * C_DIM;
    cvt_f32_f16_kernel<<<nx / 2048, 256>>>(x, (__half*)x_h, nx);
    cvt_f32_f16_kernel<<<(nq + 2047) / 2048, 256>>>(qkv_w, (__half*)qkvw_h, nq);
    cvt_f32_f16_kernel<<<(np + 2047) / 2048, 256>>>(proj_w, (__half*)projw_h, np);

    // qkv: 256m x 192n tiles -> grid (6, 256)
    dim3 g_qkv_grid(QKV_N / 192, M_TOTAL / 256);
    gemm_h_kernel<4, 3, true><<<g_qkv_grid, 384>>>(
        (const __half*)x_h, (const __half*)qkvw_h, nullptr, qkv_h, QKV_N);

    attn_kernel<<<B_DIM * 64 * N_HEADS, 128>>>();

    lepe_kernel<<<B_DIM * 64, C_DIM>>>(lepe_w, lepe_b);

    // proj: 256m x 192n tiles -> grid (2, 256)
    dim3 g_proj_grid(C_DIM / 192, M_TOTAL / 256);
    gemm_h_kernel<4, 3, false><<<g_proj_grid, 384>>>(
        (const __half*)comb_h, (const __half*)projw_h, proj_b, out, C_DIM);
}

// round 17
// speedup vs baseline: 1.0945x; 1.0945x over previous
#include <cuda_runtime.h>
#include <cuda_fp16.h>
#include <mma.h>
#include <cstdint>

using namespace nvcuda;

// ---------------------------------------------------------------------------
// LePE attention, fp16 tensor-core end-to-end (R17):
//   GEMM back to R15's 128m x 192n (2 CTAs/SM), now with a 3-stage cp.async
//   ring (wait_group 1) to hide L2 latency. LePE reads fp16 x.
// B=16, H=W=64, C=384, HEADS=12, hd=32, IDX=0 (vertical strips).
// ---------------------------------------------------------------------------

#define C_DIM   384
#define N_HEADS 12
#define HD      32
#define B_DIM   16
#define NTOK    4096
#define M_TOTAL 65536
#define QKV_N   1152

// Scratch (fp16)
__device__ __half g_x_h[(size_t)M_TOTAL * C_DIM];
__device__ __half g_qkvw_h[(size_t)QKV_N * C_DIM];
__device__ __half g_projw_h[(size_t)C_DIM * C_DIM];
__device__ __half g_qkv_h[(size_t)M_TOTAL * QKV_N];
__device__ __half g_comb_h[(size_t)M_TOTAL * C_DIM];

#define BK    32
#define PAD_H 40   // halves per smem row (80B)

__device__ __forceinline__ uint4 pack8(const float4 f0, const float4 f1) {
    __half2 h0 = __floats2half2_rn(f0.x, f0.y);
    __half2 h1 = __floats2half2_rn(f0.z, f0.w);
    __half2 h2 = __floats2half2_rn(f1.x, f1.y);
    __half2 h3 = __floats2half2_rn(f1.z, f1.w);
    uint4 u;
    u.x = *reinterpret_cast<uint32_t*>(&h0);
    u.y = *reinterpret_cast<uint32_t*>(&h1);
    u.z = *reinterpret_cast<uint32_t*>(&h2);
    u.w = *reinterpret_cast<uint32_t*>(&h3);
    return u;
}

__global__ __launch_bounds__(256) void cvt_f32_f16_kernel(
    const float* __restrict__ src, __half* __restrict__ dst, int n)
{
    const int i = (blockIdx.x * 256 + threadIdx.x) * 8;
    if (i < n) {
        float4 a = *(const float4*)(src + i);
        float4 b = *(const float4*)(src + i + 4);
        *(uint4*)(dst + i) = pack8(a, b);
    }
}

// ---------------------------------------------------------------------------
// GEMM (fp16 in): D[m,n] = sum_k A[m,k] * Bw[n,k]
// CTA tile 128m x (64*NWN)n, 2*NWN warps (2m x NWNn), warp tile 64x64.
// BK=32, 3-stage cp.async ring. Grid: blockIdx.x = n-block (fast).
// OUT_HALF: D fp16 no bias; else D fp32 + bias.
// ---------------------------------------------------------------------------
template <int NWN, bool OUT_HALF>
__global__ __launch_bounds__(32 * 2 * NWN)
void gemm_h_kernel(const __half* __restrict__ A, const __half* __restrict__ Bw,
                   const float* __restrict__ bias, void* __restrict__ Dx,
                   int ldD)
{
    constexpr int NT      = 32 * 2 * NWN;     // threads
    constexpr int N_TILE  = 64 * NWN;
    constexpr int A_UNITS = 128 * 4;          // 16B units per A chunk
    constexpr int B_UNITS = N_TILE * 4;
    constexpr int STAGES  = 3;

    __shared__ __half As[STAGES][128 * PAD_H];
    __shared__ __half Bs[STAGES][N_TILE * PAD_H];

    const int tid  = threadIdx.x;
    const int lane = tid & 31;
    const int warp = tid >> 5;                // 0 .. 2*NWN-1
    const int warpM = warp / NWN;             // 0..1
    const int warpN = warp % NWN;             // 0..NWN-1
    const int n0 = blockIdx.x * N_TILE;       // n fast
    const int m0 = blockIdx.y * 128;

    const __half* aTile = A + (size_t)m0 * C_DIM;
    const __half* bTile = Bw + (size_t)n0 * C_DIM;

    uint32_t smA[STAGES], smB[STAGES];
#pragma unroll
    for (int bfi = 0; bfi < STAGES; bfi++) {
        smA[bfi] = (uint32_t)__cvta_generic_to_shared(&As[bfi][0]);
        smB[bfi] = (uint32_t)__cvta_generic_to_shared(&Bs[bfi][0]);
    }

    wmma::fragment<wmma::accumulator, 16, 16, 16, float> acc[4][4];
#pragma unroll
    for (int tr = 0; tr < 4; tr++)
#pragma unroll
        for (int tc = 0; tc < 4; tc++)
            wmma::fill_fragment(acc[tr][tc], 0.0f);

    const int NCHUNK = C_DIM / BK;  // 12

    auto issue_chunk = [&](int c, int bfi) {
        const int k0g = c * BK;
#pragma unroll
        for (int u = tid; u < A_UNITS; u += NT) {
            const int row = u >> 2, q = u & 3;
            asm volatile("cp.async.cg.shared.global [%0], [%1], 16;"
                :: "r"(smA[bfi] + (row * PAD_H + q * 8) * 2),
                   "l"(aTile + (size_t)row * C_DIM + k0g + q * 8) : "memory");
        }
#pragma unroll
        for (int u = tid; u < B_UNITS; u += NT) {
            const int row = u >> 2, q = u & 3;
            asm volatile("cp.async.cg.shared.global [%0], [%1], 16;"
                :: "r"(smB[bfi] + (row * PAD_H + q * 8) * 2),
                   "l"(bTile + (size_t)row * C_DIM + k0g + q * 8) : "memory");
        }
        asm volatile("cp.async.commit_group;" ::: "memory");
    };

    issue_chunk(0, 0);
    issue_chunk(1, 1);

    int sbuf = 0;
    for (int c = 0; c < NCHUNK; c++) {
        // chunk c complete when at most 1 group (chunk c+1) still pending
        asm volatile("cp.async.wait_group 1;" ::: "memory");
        __syncthreads();   // also: all warps done computing chunk c-1

        if (c + 2 < NCHUNK) {
            int nb = sbuf + 2; if (nb >= STAGES) nb -= STAGES;
            issue_chunk(c + 2, nb);
        }

        const __half* sa = As[sbuf];
        const __half* sb = Bs[sbuf];
#pragma unroll
        for (int ks = 0; ks < 2; ks++) {
            const int k0 = ks * 16;
            wmma::fragment<wmma::matrix_a, 16, 16, 16, __half,
                           wmma::row_major> af[4];
#pragma unroll
            for (int tr = 0; tr < 4; tr++)
                wmma::load_matrix_sync(af[tr],
                    sa + (warpM * 64 + tr * 16) * PAD_H + k0, PAD_H);
#pragma unroll
            for (int tc = 0; tc < 4; tc++) {
                wmma::fragment<wmma::matrix_b, 16, 16, 16, __half,
                               wmma::col_major> bf;
                wmma::load_matrix_sync(bf,
                    sb + (warpN * 64 + tc * 16) * PAD_H + k0, PAD_H);
#pragma unroll
                for (int tr = 0; tr < 4; tr++)
                    wmma::mma_sync(acc[tr][tc], af[tr], bf, acc[tr][tc]);
            }
        }
        if (++sbuf == STAGES) sbuf = 0;
    }
    __syncthreads();

    // epilogue: per-warp 16x16 fp32 staging in As region
    float* stage = reinterpret_cast<float*>(&As[0][0]) + warp * 256;
#pragma unroll
    for (int tr = 0; tr < 4; tr++) {
#pragma unroll
        for (int tc = 0; tc < 4; tc++) {
            const int mBase = m0 + warpM * 64 + tr * 16;
            const int nBase = n0 + warpN * 64 + tc * 16;
            wmma::store_matrix_sync(stage, acc[tr][tc], 16, wmma::mem_row_major);
            __syncwarp();
            if (OUT_HALF) {
                __half* Dh = (__half*)Dx;
#pragma unroll
                for (int t = 0; t < 2; t++) {
                    const int idx = t * 32 + lane;
                    const int r  = idx >> 2;
                    const int c4 = idx & 3;
                    const float* sp = stage + r * 16 + c4 * 4;
                    __half2 h0 = __floats2half2_rn(sp[0], sp[1]);
                    __half2 h1 = __floats2half2_rn(sp[2], sp[3]);
                    uint2 u;
                    u.x = *reinterpret_cast<uint32_t*>(&h0);
                    u.y = *reinterpret_cast<uint32_t*>(&h1);
                    *(uint2*)&Dh[(size_t)(mBase + r) * ldD + nBase + c4 * 4] = u;
                }
            } else {
                float* Df = (float*)Dx;
#pragma unroll
                for (int t = 0; t < 2; t++) {
                    const int idx = t * 32 + lane;
                    const int r  = idx >> 2;
                    const int c4 = idx & 3;
                    float4 v = *(const float4*)(stage + r * 16 + c4 * 4);
                    const float4 b4 = *(const float4*)&bias[nBase + c4 * 4];
                    v.x += b4.x; v.y += b4.y; v.z += b4.z; v.w += b4.w;
                    *(float4*)&Df[(size_t)(mBase + r) * ldD + nBase + c4 * 4] = v;
                }
            }
            __syncwarp();
        }
    }
}

// ---------------------------------------------------------------------------
// Attention via WMMA fp16: one block per (s, head), 128 threads / 4 warps.
// ---------------------------------------------------------------------------
__global__ __launch_bounds__(128) void attn_kernel()
{
    __shared__ __half Qh[64][PAD_H];
    __shared__ __half Kh[64][PAD_H];
    __shared__ __half Vh[64][PAD_H];
    __shared__ float  S[64][68];
    __shared__ __half Ph[64][72];

    const int g    = blockIdx.x;
    const int tid  = threadIdx.x;
    const int warp = tid >> 5, lane = tid & 31;
    const int s    = g / N_HEADS;
    const int head = g - s * N_HEADS;
    const int b    = s >> 6;
    const int w    = s & 63;
    const int cBase = head * HD;

    const size_t rowBase = (size_t)(b << 12) + w;
    for (int i = tid; i < 256; i += 128) {
        const int l = i >> 2, grp = i & 3;
        const size_t off = (rowBase + (size_t)l * 64) * QKV_N + cBase + grp * 8;
        *(uint4*)&Qh[l][grp * 8] = *(const uint4*)&g_qkv_h[off];
        *(uint4*)&Kh[l][grp * 8] = *(const uint4*)&g_qkv_h[off + C_DIM];
        *(uint4*)&Vh[l][grp * 8] = *(const uint4*)&g_qkv_h[off + 2 * C_DIM];
    }
    __syncthreads();

    {
        wmma::fragment<wmma::matrix_a, 16, 16, 16, __half, wmma::row_major> aq[2];
        wmma::load_matrix_sync(aq[0], &Qh[warp * 16][0], PAD_H);
        wmma::load_matrix_sync(aq[1], &Qh[warp * 16][16], PAD_H);
#pragma unroll
        for (int nt = 0; nt < 4; nt++) {
            wmma::fragment<wmma::accumulator, 16, 16, 16, float> accS;
            wmma::fill_fragment(accS, 0.0f);
#pragma unroll
            for (int k0 = 0; k0 < 2; k0++) {
                wmma::fragment<wmma::matrix_b, 16, 16, 16, __half,
                               wmma::col_major> bk;
                wmma::load_matrix_sync(bk, &Kh[nt * 16][k0 * 16], PAD_H);
                wmma::mma_sync(accS, aq[k0], bk, accS);
            }
            wmma::store_matrix_sync(&S[warp * 16][nt * 16], accS, 68,
                                    wmma::mem_row_major);
        }
    }
    __syncwarp();

    const float scale = 0.17677669529663687f;
#pragma unroll
    for (int r = 0; r < 16; r++) {
        const int l = warp * 16 + r;
        float v0 = S[l][lane] * scale, v1 = S[l][lane + 32] * scale;
        float mx = fmaxf(v0, v1);
#pragma unroll
        for (int o = 16; o; o >>= 1) mx = fmaxf(mx, __shfl_xor_sync(0xFFFFFFFFu, mx, o));
        const float e0 = __expf(v0 - mx);
        const float e1 = __expf(v1 - mx);
        float sm = e0 + e1;
#pragma unroll
        for (int o = 16; o; o >>= 1) sm += __shfl_xor_sync(0xFFFFFFFFu, sm, o);
        const float inv = 1.f / sm;
        Ph[l][lane]      = __float2half(e0 * inv);
        Ph[l][lane + 32] = __float2half(e1 * inv);
    }
    __syncwarp();

    {
        wmma::fragment<wmma::matrix_a, 16, 16, 16, __half, wmma::row_major> ap[4];
#pragma unroll
        for (int k0 = 0; k0 < 4; k0++)
            wmma::load_matrix_sync(ap[k0], &Ph[warp * 16][k0 * 16], 72);
#pragma unroll
        for (int nt = 0; nt < 2; nt++) {
            wmma::fragment<wmma::accumulator, 16, 16, 16, float> accO;
            wmma::fill_fragment(accO, 0.0f);
#pragma unroll
            for (int k0 = 0; k0 < 4; k0++) {
                wmma::fragment<wmma::matrix_b, 16, 16, 16, __half,
                               wmma::row_major> bv;
                wmma::load_matrix_sync(bv, &Vh[k0 * 16][nt * 16], PAD_H);
                wmma::mma_sync(accO, ap[k0], bv, accO);
            }
            wmma::store_matrix_sync(&S[warp * 16][nt * 16], accO, 68,
                                    wmma::mem_row_major);
        }
    }
    __syncwarp();

    __half* dstBase = g_comb_h +
        ((size_t)(b << 12) + (w << 6) + warp * 16) * C_DIM + cBase;
    for (int idx = lane; idx < 128; idx += 32) {
        const int r = idx >> 3, grp = idx & 7;
        const float* sp = &S[warp * 16 + r][grp * 4];
        __half2 h0 = __floats2half2_rn(sp[0], sp[1]);
        __half2 h1 = __floats2half2_rn(sp[2], sp[3]);
        uint2 u;
        u.x = *reinterpret_cast<uint32_t*>(&h0);
        u.y = *reinterpret_cast<uint32_t*>(&h1);
        *(uint2*)&dstBase[(size_t)r * C_DIM + grp * 4] = u;
    }
}

// ---------------------------------------------------------------------------
// LePE: depthwise 3x3, register-rotation, reads fp16 g_x_h.
// One block per (b, hh); 384 threads = channels. fp16 += into g_comb_h.
// ---------------------------------------------------------------------------
__global__ __launch_bounds__(C_DIM) void lepe_kernel(
    const float* __restrict__ lw, const float* __restrict__ lb)
{
    const int blk = blockIdx.x;       // b*64 + hh
    const int c   = threadIdx.x;
    const int b   = blk >> 6;
    const int hh  = blk & 63;

    float w9[9];
#pragma unroll
    for (int k = 0; k < 9; k++) w9[k] = lw[c * 9 + k];
    const float bch = lb[c];

    const __half* xrow[3];
    bool valid[3];
#pragma unroll
    for (int j = 0; j < 3; j++) {
        const int y = hh - 1 + j;
        valid[j] = (y >= 0 && y < 64);
        xrow[j] = g_x_h + (size_t)((b << 12) + (y << 6)) * C_DIM + c;
    }

    float xm1[3], x0[3], xp1[3];
#pragma unroll
    for (int j = 0; j < 3; j++) {
        xm1[j] = 0.f;
        x0[j]  = valid[j] ? __half2float(xrow[j][0]) : 0.f;
        xp1[j] = valid[j] ? __half2float(xrow[j][C_DIM]) : 0.f;
    }

    __half* crow = g_comb_h + (size_t)((b << 12) + (hh << 6)) * C_DIM + c;

    for (int ww = 0; ww < 64; ww++) {
        float acc = bch;
#pragma unroll
        for (int j = 0; j < 3; j++)
            acc += xm1[j] * w9[j * 3 + 0] + x0[j] * w9[j * 3 + 1] +
                   xp1[j] * w9[j * 3 + 2];
        const size_t oi = (size_t)ww * C_DIM;
        crow[oi] = __float2half(__half2float(crow[oi]) + acc);

#pragma unroll
        for (int j = 0; j < 3; j++) {
            xm1[j] = x0[j];
            x0[j]  = xp1[j];
            const int nxt = ww + 2;
            xp1[j] = (nxt < 64 && valid[j])
                     ? __half2float(xrow[j][(size_t)nxt * C_DIM]) : 0.f;
        }
    }
}

// ---------------------------------------------------------------------------
extern "C" void kernel_launch(void* const* d_in, const int* in_sizes, int n_in,
                              void* d_out, int out_size)
{
    const float* x      = (const float*)d_in[0];
    const float* qkv_w  = (const float*)d_in[1];
    const float* proj_w = (const float*)d_in[2];
    const float* proj_b = (const float*)d_in[3];
    const float* lepe_w = (const float*)d_in[4];
    const float* lepe_b = (const float*)d_in[5];
    float* out = (float*)d_out;
    (void)in_sizes; (void)n_in; (void)out_size;

    void *x_h, *qkvw_h, *projw_h, *qkv_h, *comb_h;
    cudaGetSymbolAddress(&x_h, g_x_h);
    cudaGetSymbolAddress(&qkvw_h, g_qkvw_h);
    cudaGetSymbolAddress(&projw_h, g_projw_h);
    cudaGetSymbolAddress(&qkv_h, g_qkv_h);
    cudaGetSymbolAddress(&comb_h, g_comb_h);

    const int nx = M_TOTAL * C_DIM;
    const int nq = QKV_N * C_DIM;
    const int np = C_DIM * C_DIM;
    cvt_f32_f16_kernel<<<nx / 2048, 256>>>(x, (__half*)x_h, nx);
    cvt_f32_f16_kernel<<<(nq + 2047) / 2048, 256>>>(qkv_w, (__half*)qkvw_h, nq);
    cvt_f32_f16_kernel<<<(np + 2047) / 2048, 256>>>(proj_w, (__half*)projw_h, np);

    // qkv: 128m x 192n tiles -> grid (6, 512)
    dim3 g_qkv_grid(QKV_N / 192, M_TOTAL / 128);
    gemm_h_kernel<3, true><<<g_qkv_grid, 192>>>(
        (const __half*)x_h, (const __half*)qkvw_h, nullptr, qkv_h, QKV_N);

    attn_kernel<<<B_DIM * 64 * N_HEADS, 128>>>();

    lepe_kernel<<<B_DIM * 64, C_DIM>>>(lepe_w, lepe_b);

    // proj: 128m x 192n tiles -> grid (2, 512)
    dim3 g_proj_grid(C_DIM / 192, M_TOTAL / 128);
    gemm_h_kernel<3, false><<<g_proj_grid, 192>>>(
        (const __half*)comb_h, (const __half*)projw_h, proj_b, out, C_DIM);
}